// round 2
// baseline (speedup 1.0000x reference)
#include <cuda_runtime.h>
#include <stdint.h>
#include <stddef.h>

#define N_NODES 10000
#define DIM 40
#define KSEL 32
#define ALPHA 3.0f
#define JTILE 64
#define RPB 8          // rows per block (one warp per row)

// ---------------- device scratch (no allocation allowed) ----------------
__device__ float g_P[N_NODES * DIM];   // nv1
__device__ float g_Q[N_NODES * DIM];   // nv2
__device__ int   g_flag[N_NODES];      // rows needing exact fallback

// ---------------- XLA EmitFastTanh replica (with-FMA variant) ----------------
__device__ __forceinline__ float xla_tanh(float x) {
    const float kClamp = 7.99881172180175781f;
    float ax = fabsf(x);
    float xc = fminf(fmaxf(x, -kClamp), kClamp);
    float x2 = xc * xc;
    float num = -2.76076847742355e-16f;
    num = fmaf(x2, num,  2.00018790482477e-13f);
    num = fmaf(x2, num, -8.60467152213735e-11f);
    num = fmaf(x2, num,  5.12229709037114e-08f);
    num = fmaf(x2, num,  1.48572235717979e-05f);
    num = fmaf(x2, num,  6.37261928875436e-04f);
    num = fmaf(x2, num,  4.89352455891786e-03f);
    num = xc * num;
    float den = 1.19825839466702e-06f;
    den = fmaf(x2, den, 1.18534705686654e-04f);
    den = fmaf(x2, den, 2.26843463243900e-03f);
    den = fmaf(x2, den, 4.89352518554385e-03f);
    float r = num / den;
    return (ax < 0.0004f) ? x : r;
}

// ---------------- kernel 1: nv prep + flag reset ----------------
__global__ void prep_kernel(const int* __restrict__ idx,
                            const float* __restrict__ emb1,
                            const float* __restrict__ emb2,
                            const float* __restrict__ W1,
                            const float* __restrict__ b1,
                            const float* __restrict__ W2,
                            const float* __restrict__ b2) {
    __shared__ float sW1[DIM * DIM];
    __shared__ float sW2[DIM * DIM];
    __shared__ float sb[2 * DIM];
    for (int e = threadIdx.x; e < DIM * DIM; e += blockDim.x) {
        sW1[e] = W1[e];
        sW2[e] = W2[e];
    }
    if (threadIdx.x < DIM) {
        sb[threadIdx.x]       = b1[threadIdx.x];
        sb[DIM + threadIdx.x] = b2[threadIdx.x];
    }
    __syncthreads();

    int gt = blockIdx.x * blockDim.x + threadIdx.x;
    if (gt < N_NODES) g_flag[gt] = 0;
    if (gt >= N_NODES * DIM) return;

    int i = gt / DIM, d = gt % DIM;
    int s = idx[i];
    const float* e1 = emb1 + (size_t)s * DIM;
    const float* e2 = emb2 + (size_t)s * DIM;
    float z1 = 0.f, z2 = 0.f;
#pragma unroll
    for (int k = 0; k < DIM; k++) {
        z1 = fmaf(e1[k], sW1[d * DIM + k], z1);
        z2 = fmaf(e2[k], sW2[d * DIM + k], z2);
    }
    z1 += sb[d];
    z2 += sb[DIM + d];
    g_P[i * DIM + d] = xla_tanh(ALPHA * z1);
    g_Q[i * DIM + d] = xla_tanh(ALPHA * z2);
}

// ---------------- kernel 2: fused zero-fill + first-32-saturated scan ----------------
__global__ void __launch_bounds__(RPB * 32) scan_kernel(float* __restrict__ out) {
    __shared__ float sP[RPB][DIM];
    __shared__ float sQ[RPB][DIM];
    __shared__ float tP[DIM][JTILE];
    __shared__ float tQ[DIM][JTILE];
    __shared__ int s_done;

    const int tid  = threadIdx.x;
    const int lane = tid & 31;
    const int w    = tid >> 5;
    const int row0 = blockIdx.x * RPB;
    const int row  = row0 + w;

    // zero this warp's output row (10000 floats = 2500 float4, 16B aligned)
    {
        float4* orow = reinterpret_cast<float4*>(out + (size_t)row * N_NODES);
        float4 z = make_float4(0.f, 0.f, 0.f, 0.f);
        for (int t = lane; t < N_NODES / 4; t += 32) orow[t] = z;
    }

    // stage own-row vectors
    for (int e = tid; e < RPB * DIM; e += RPB * 32) {
        int r = e / DIM, k = e % DIM;
        sP[r][k] = g_P[(row0 + r) * DIM + k];
        sQ[r][k] = g_Q[(row0 + r) * DIM + k];
    }
    if (tid == 0) s_done = 0;
    __syncthreads();

    float rP[DIM], rQ[DIM];
#pragma unroll
    for (int k = 0; k < DIM; k++) { rP[k] = sP[w][k]; rQ[k] = sQ[w][k]; }

    const float C = xla_tanh(8.0f);   // saturated fast-tanh value
    int  hits = 0;
    bool done = false;
    const int ntiles = (N_NODES + JTILE - 1) / JTILE;

    for (int t = 0; t < ntiles; t++) {
        const int j0 = t * JTILE;
        // cooperative tile load (transposed, conflict-free on read)
        for (int e = tid; e < DIM * JTILE; e += RPB * 32) {
            int k = e / JTILE, j = e % JTILE;
            int gj = j0 + j;
            float vp = 0.f, vq = 0.f;
            if (gj < N_NODES) {
                vp = g_P[gj * DIM + k];
                vq = g_Q[gj * DIM + k];
            }
            tP[k][j] = vp;
            tQ[k][j] = vq;
        }
        __syncthreads();

        if (!done) {
#pragma unroll
            for (int q = 0; q < JTILE / 32; q++) {
                const int jt = q * 32 + lane;
                const int j  = j0 + jt;
                float d1 = 0.f, d2 = 0.f;
#pragma unroll
                for (int k = 0; k < DIM; k++) {
                    d1 = fmaf(rP[k], tQ[k][jt], d1);
                    d2 = fmaf(rQ[k], tP[k][jt], d2);
                }
                float a   = d1 - d2;
                float val = xla_tanh(ALPHA * a);
                bool pred = (j < N_NODES) && (val >= C);
                unsigned m = __ballot_sync(0xffffffffu, pred);
                int rank = __popc(m & ((1u << lane) - 1u));
                if (pred && (hits + rank) < KSEL)
                    out[(size_t)row * N_NODES + j] = val;
                hits += __popc(m);
                if (hits >= KSEL) break;
            }
            if (hits >= KSEL) {
                done = true;
                if (lane == 0) atomicAdd(&s_done, 1);
            }
        }
        __syncthreads();
        if (s_done == RPB) break;
    }

    if (hits < KSEL && lane == 0) g_flag[row] = 1;   // exact fallback needed
}

// ---------------- kernel 3: exact stable top-32 fallback (rarely/never runs) ----------------
__global__ void fallback_kernel(float* __restrict__ out) {
    const int row = blockIdx.x;
    if (!g_flag[row]) return;

    const int tid = threadIdx.x;                 // 256 threads
    const int lane = tid & 31, w = tid >> 5;
    constexpr int CPT = (N_NODES + 255) / 256;   // 40 columns per thread

    __shared__ unsigned long long warpmax[8];
    __shared__ unsigned long long s_best;

    float rP[DIM], rQ[DIM];
#pragma unroll
    for (int k = 0; k < DIM; k++) {
        rP[k] = g_P[row * DIM + k];
        rQ[k] = g_Q[row * DIM + k];
    }

    float vals[CPT];
#pragma unroll
    for (int c = 0; c < CPT; c++) {
        int j = tid + c * 256;
        float v = -1.f;
        if (j < N_NODES) {
            float d1 = 0.f, d2 = 0.f;
            for (int k = 0; k < DIM; k++) {
                d1 = fmaf(rP[k], g_Q[j * DIM + k], d1);
                d2 = fmaf(rQ[k], g_P[j * DIM + k], d2);
            }
            v = fmaxf(0.f, xla_tanh(ALPHA * (d1 - d2)));
        }
        vals[c] = v;
    }

    unsigned long long chosen = 0ull;
    for (int it = 0; it < KSEL; it++) {
        unsigned long long best = 0ull;
#pragma unroll
        for (int c = 0; c < CPT; c++) {
            int j = tid + c * 256;
            if (j < N_NODES && !((chosen >> c) & 1ull) && vals[c] >= 0.f) {
                unsigned long long key =
                    ((unsigned long long)__float_as_uint(vals[c]) << 32) |
                    (unsigned long long)(0xFFFFFFFFu - (unsigned)j);
                if (key > best) best = key;
            }
        }
#pragma unroll
        for (int off = 16; off > 0; off >>= 1) {
            unsigned long long o = __shfl_down_sync(0xffffffffu, best, off);
            if (o > best) best = o;
        }
        if (lane == 0) warpmax[w] = best;
        __syncthreads();
        if (tid == 0) {
            unsigned long long b = warpmax[0];
            for (int i = 1; i < 8; i++) if (warpmax[i] > b) b = warpmax[i];
            s_best = b;
        }
        __syncthreads();
        unsigned long long gb = s_best;
        int widx = (int)(0xFFFFFFFFu - (unsigned)(gb & 0xFFFFFFFFu));
        if ((widx & 255) == tid) {
            chosen |= 1ull << (widx >> 8);
            out[(size_t)row * N_NODES + widx] = __uint_as_float((unsigned)(gb >> 32));
        }
        __syncthreads();
    }
}

// ---------------- launch ----------------
extern "C" void kernel_launch(void* const* d_in, const int* in_sizes, int n_in,
                              void* d_out, int out_size) {
    const int*   idx  = (const int*)  d_in[0];
    const float* emb1 = (const float*)d_in[1];
    const float* emb2 = (const float*)d_in[2];
    const float* W1   = (const float*)d_in[3];
    const float* b1   = (const float*)d_in[4];
    const float* W2   = (const float*)d_in[5];
    const float* b2   = (const float*)d_in[6];
    float* out = (float*)d_out;

    (void)in_sizes; (void)n_in; (void)out_size;

    int prep_blocks = (N_NODES * DIM + 255) / 256;
    prep_kernel<<<prep_blocks, 256>>>(idx, emb1, emb2, W1, b1, W2, b2);
    scan_kernel<<<N_NODES / RPB, RPB * 32>>>(out);
    fallback_kernel<<<N_NODES, 256>>>(out);
}

// round 3
// speedup vs baseline: 1.1309x; 1.1309x over previous
#include <cuda_runtime.h>
#include <stdint.h>
#include <stddef.h>

#define N_NODES 10000
#define DIM 40
#define KSEL 32
#define ALPHA 3.0f
#define JTILE 64
#define RPB 8          // rows per block in scan (one warp per row)
#define PREP_ROWS 8    // rows per block in prep

// ---------------- device scratch (no allocation allowed) ----------------
__device__ float g_P[N_NODES * DIM];   // nv1
__device__ float g_Q[N_NODES * DIM];   // nv2
__device__ int   g_fail[N_NODES];      // compacted list of rows needing exact fallback
__device__ int   g_nfail;

// ---------------- XLA EmitFastTanh replica (with-FMA variant) ----------------
__device__ __forceinline__ float xla_tanh(float x) {
    const float kClamp = 7.99881172180175781f;
    float ax = fabsf(x);
    float xc = fminf(fmaxf(x, -kClamp), kClamp);
    float x2 = xc * xc;
    float num = -2.76076847742355e-16f;
    num = fmaf(x2, num,  2.00018790482477e-13f);
    num = fmaf(x2, num, -8.60467152213735e-11f);
    num = fmaf(x2, num,  5.12229709037114e-08f);
    num = fmaf(x2, num,  1.48572235717979e-05f);
    num = fmaf(x2, num,  6.37261928875436e-04f);
    num = fmaf(x2, num,  4.89352455891786e-03f);
    num = xc * num;
    float den = 1.19825839466702e-06f;
    den = fmaf(x2, den, 1.18534705686654e-04f);
    den = fmaf(x2, den, 2.26843463243900e-03f);
    den = fmaf(x2, den, 4.89352518554385e-03f);
    float r = num / den;
    return (ax < 0.0004f) ? x : r;
}

// ---------------- kernel 0: streaming zero-fill of the 400 MB output ----------------
__global__ void __launch_bounds__(256) zero_kernel(float4* __restrict__ out4, int n4) {
    if (blockIdx.x == 0 && threadIdx.x == 0) g_nfail = 0;
    int i = blockIdx.x * blockDim.x + threadIdx.x;
    const int stride = gridDim.x * blockDim.x;
    const float4 z = make_float4(0.f, 0.f, 0.f, 0.f);
    for (; i < n4; i += stride) __stcs(&out4[i], z);
}

// ---------------- kernel 1: nv prep (shared-staged, transposed W) ----------------
__global__ void __launch_bounds__(PREP_ROWS * DIM) prep_kernel(
        const int* __restrict__ idx,
        const float* __restrict__ emb1,
        const float* __restrict__ emb2,
        const float* __restrict__ W1,
        const float* __restrict__ b1,
        const float* __restrict__ W2,
        const float* __restrict__ b2) {
    __shared__ float sW1t[DIM * DIM];   // [k][d] transposed
    __shared__ float sW2t[DIM * DIM];
    __shared__ float sb[2 * DIM];
    __shared__ float se1[PREP_ROWS][DIM];
    __shared__ float se2[PREP_ROWS][DIM];

    const int tid  = threadIdx.x;                 // 320 threads
    const int row0 = blockIdx.x * PREP_ROWS;

    for (int e = tid; e < DIM * DIM; e += PREP_ROWS * DIM) {
        int d = e / DIM, k = e % DIM;
        sW1t[k * DIM + d] = W1[e];
        sW2t[k * DIM + d] = W2[e];
    }
    if (tid < DIM) {
        sb[tid]       = b1[tid];
        sb[DIM + tid] = b2[tid];
    }
    // gather embedding rows for this block
    {
        int i = tid / DIM, k = tid % DIM;
        int gi = row0 + i;
        if (gi < N_NODES) {
            int s = idx[gi];
            se1[i][k] = emb1[(size_t)s * DIM + k];
            se2[i][k] = emb2[(size_t)s * DIM + k];
        }
    }
    __syncthreads();

    const int i = tid / DIM, d = tid % DIM;
    const int gi = row0 + i;
    if (gi >= N_NODES) return;

    float z1 = 0.f, z2 = 0.f;
#pragma unroll
    for (int k = 0; k < DIM; k++) {
        z1 = fmaf(se1[i][k], sW1t[k * DIM + d], z1);
        z2 = fmaf(se2[i][k], sW2t[k * DIM + d], z2);
    }
    z1 += sb[d];
    z2 += sb[DIM + d];
    g_P[gi * DIM + d] = xla_tanh(ALPHA * z1);
    g_Q[gi * DIM + d] = xla_tanh(ALPHA * z2);
}

// ---------------- kernel 2: first-32-saturated scan, direct writes ----------------
__global__ void __launch_bounds__(RPB * 32) scan_kernel(float* __restrict__ out) {
    __shared__ float sP[RPB][DIM];
    __shared__ float sQ[RPB][DIM];
    __shared__ float tP[DIM][JTILE];
    __shared__ float tQ[DIM][JTILE];
    __shared__ int s_done;

    const int tid  = threadIdx.x;
    const int lane = tid & 31;
    const int w    = tid >> 5;
    const int row0 = blockIdx.x * RPB;
    const int row  = row0 + w;

    for (int e = tid; e < RPB * DIM; e += RPB * 32) {
        int r = e / DIM, k = e % DIM;
        sP[r][k] = g_P[(row0 + r) * DIM + k];
        sQ[r][k] = g_Q[(row0 + r) * DIM + k];
    }
    if (tid == 0) s_done = 0;
    __syncthreads();

    float rP[DIM], rQ[DIM];
#pragma unroll
    for (int k = 0; k < DIM; k++) { rP[k] = sP[w][k]; rQ[k] = sQ[w][k]; }

    const float C = xla_tanh(8.0f);   // saturated fast-tanh value
    int  hits = 0;
    bool done = false;
    const int ntiles = (N_NODES + JTILE - 1) / JTILE;

    for (int t = 0; t < ntiles; t++) {
        const int j0 = t * JTILE;
        for (int e = tid; e < DIM * JTILE; e += RPB * 32) {
            int k = e / JTILE, j = e % JTILE;
            int gj = j0 + j;
            float vp = 0.f, vq = 0.f;
            if (gj < N_NODES) {
                vp = g_P[gj * DIM + k];
                vq = g_Q[gj * DIM + k];
            }
            tP[k][j] = vp;
            tQ[k][j] = vq;
        }
        __syncthreads();

        if (!done) {
#pragma unroll
            for (int q = 0; q < JTILE / 32; q++) {
                const int jt = q * 32 + lane;
                const int j  = j0 + jt;
                float d1 = 0.f, d2 = 0.f;
#pragma unroll
                for (int k = 0; k < DIM; k++) {
                    d1 = fmaf(rP[k], tQ[k][jt], d1);
                    d2 = fmaf(rQ[k], tP[k][jt], d2);
                }
                float a   = d1 - d2;
                float val = xla_tanh(ALPHA * a);
                bool pred = (j < N_NODES) && (val >= C);
                unsigned m = __ballot_sync(0xffffffffu, pred);
                int rank = __popc(m & ((1u << lane) - 1u));
                if (pred && (hits + rank) < KSEL)
                    out[(size_t)row * N_NODES + j] = val;
                hits += __popc(m);
                if (hits >= KSEL) break;
            }
            if (hits >= KSEL) {
                done = true;
                if (lane == 0) atomicAdd(&s_done, 1);
            }
        }
        __syncthreads();
        if (s_done == RPB) break;
    }

    if (hits < KSEL && lane == 0) {
        int slot = atomicAdd(&g_nfail, 1);
        g_fail[slot] = row;
    }
}

// ---------------- kernel 3: exact stable top-32 fallback over fail list ----------------
__global__ void __launch_bounds__(256) fallback_kernel(float* __restrict__ out) {
    const int tid = threadIdx.x, lane = tid & 31, w = tid >> 5;
    constexpr int CPT = (N_NODES + 255) / 256;   // 40 columns per thread

    __shared__ unsigned long long warpmax[8];
    __shared__ unsigned long long s_best;

    const int nfail = g_nfail;
    for (int t = blockIdx.x; t < nfail; t += gridDim.x) {
        const int row = g_fail[t];

        float rP[DIM], rQ[DIM];
#pragma unroll
        for (int k = 0; k < DIM; k++) {
            rP[k] = g_P[row * DIM + k];
            rQ[k] = g_Q[row * DIM + k];
        }

        float vals[CPT];
#pragma unroll
        for (int c = 0; c < CPT; c++) {
            int j = tid + c * 256;
            float v = -1.f;
            if (j < N_NODES) {
                float d1 = 0.f, d2 = 0.f;
                for (int k = 0; k < DIM; k++) {
                    d1 = fmaf(rP[k], g_Q[j * DIM + k], d1);
                    d2 = fmaf(rQ[k], g_P[j * DIM + k], d2);
                }
                v = fmaxf(0.f, xla_tanh(ALPHA * (d1 - d2)));
            }
            vals[c] = v;
        }

        unsigned long long chosen = 0ull;
        for (int it = 0; it < KSEL; it++) {
            unsigned long long best = 0ull;
#pragma unroll
            for (int c = 0; c < CPT; c++) {
                int j = tid + c * 256;
                if (j < N_NODES && !((chosen >> c) & 1ull) && vals[c] >= 0.f) {
                    unsigned long long key =
                        ((unsigned long long)__float_as_uint(vals[c]) << 32) |
                        (unsigned long long)(0xFFFFFFFFu - (unsigned)j);
                    if (key > best) best = key;
                }
            }
#pragma unroll
            for (int off = 16; off > 0; off >>= 1) {
                unsigned long long o = __shfl_down_sync(0xffffffffu, best, off);
                if (o > best) best = o;
            }
            if (lane == 0) warpmax[w] = best;
            __syncthreads();
            if (tid == 0) {
                unsigned long long b = warpmax[0];
                for (int i = 1; i < 8; i++) if (warpmax[i] > b) b = warpmax[i];
                s_best = b;
            }
            __syncthreads();
            unsigned long long gb = s_best;
            int widx = (int)(0xFFFFFFFFu - (unsigned)(gb & 0xFFFFFFFFu));
            if ((widx & 255) == tid) {
                chosen |= 1ull << (widx >> 8);
                out[(size_t)row * N_NODES + widx] = __uint_as_float((unsigned)(gb >> 32));
            }
            __syncthreads();
        }
        __syncthreads();
    }
}

// ---------------- launch ----------------
extern "C" void kernel_launch(void* const* d_in, const int* in_sizes, int n_in,
                              void* d_out, int out_size) {
    const int*   idx  = (const int*)  d_in[0];
    const float* emb1 = (const float*)d_in[1];
    const float* emb2 = (const float*)d_in[2];
    const float* W1   = (const float*)d_in[3];
    const float* b1   = (const float*)d_in[4];
    const float* W2   = (const float*)d_in[5];
    const float* b2   = (const float*)d_in[6];
    float* out = (float*)d_out;

    (void)in_sizes; (void)n_in; (void)out_size;

    const int n4 = (N_NODES * N_NODES) / 4;           // 25,000,000 float4
    zero_kernel<<<4096, 256>>>((float4*)out, n4);

    const int prep_grid = (N_NODES + PREP_ROWS - 1) / PREP_ROWS;
    prep_kernel<<<prep_grid, PREP_ROWS * DIM>>>(idx, emb1, emb2, W1, b1, W2, b2);

    scan_kernel<<<N_NODES / RPB, RPB * 32>>>(out);

    fallback_kernel<<<128, 256>>>(out);
}

// round 4
// speedup vs baseline: 1.1364x; 1.0048x over previous
#include <cuda_runtime.h>
#include <stdint.h>
#include <stddef.h>

#define N_NODES 10000
#define DIM 40
#define KSEL 32
#define ALPHA 3.0f
#define JTILE 64
#define RPB 8          // rows per scan block (one warp per row)
#define PREP_ROWS 8
#define NSCAN (N_NODES / RPB)      // 1250 scan blocks
#define NZERO 2500                 // zero blocks
#define GRIDB (NSCAN + NZERO)      // 3750, interleaved bid%3==0 -> scan

// ---------------- device scratch (no allocation allowed) ----------------
__device__ float g_P[N_NODES * DIM];
__device__ float g_Q[N_NODES * DIM];
__device__ float g_hval[N_NODES * KSEL];   // compact hit values
__device__ int   g_hidx[N_NODES * KSEL];   // compact hit column indices
__device__ int   g_hcnt[N_NODES];          // hits written (<= KSEL)
__device__ int   g_fail[N_NODES];
__device__ int   g_nfail;

// ---------------- XLA EmitFastTanh replica (with-FMA variant) ----------------
__device__ __forceinline__ float xla_tanh(float x) {
    const float kClamp = 7.99881172180175781f;
    float ax = fabsf(x);
    float xc = fminf(fmaxf(x, -kClamp), kClamp);
    float x2 = xc * xc;
    float num = -2.76076847742355e-16f;
    num = fmaf(x2, num,  2.00018790482477e-13f);
    num = fmaf(x2, num, -8.60467152213735e-11f);
    num = fmaf(x2, num,  5.12229709037114e-08f);
    num = fmaf(x2, num,  1.48572235717979e-05f);
    num = fmaf(x2, num,  6.37261928875436e-04f);
    num = fmaf(x2, num,  4.89352455891786e-03f);
    num = xc * num;
    float den = 1.19825839466702e-06f;
    den = fmaf(x2, den, 1.18534705686654e-04f);
    den = fmaf(x2, den, 2.26843463243900e-03f);
    den = fmaf(x2, den, 4.89352518554385e-03f);
    float r = num / den;
    return (ax < 0.0004f) ? x : r;
}

// ---------------- kernel 1: nv prep (shared-staged, transposed W) ----------------
__global__ void __launch_bounds__(PREP_ROWS * DIM) prep_kernel(
        const int* __restrict__ idx,
        const float* __restrict__ emb1,
        const float* __restrict__ emb2,
        const float* __restrict__ W1,
        const float* __restrict__ b1,
        const float* __restrict__ W2,
        const float* __restrict__ b2) {
    __shared__ float sW1t[DIM * DIM];
    __shared__ float sW2t[DIM * DIM];
    __shared__ float sb[2 * DIM];
    __shared__ float se1[PREP_ROWS][DIM];
    __shared__ float se2[PREP_ROWS][DIM];

    const int tid  = threadIdx.x;               // 320 threads
    const int row0 = blockIdx.x * PREP_ROWS;

    if (blockIdx.x == 0 && tid == 0) g_nfail = 0;

    for (int e = tid; e < DIM * DIM; e += PREP_ROWS * DIM) {
        int d = e / DIM, k = e % DIM;
        sW1t[k * DIM + d] = W1[e];
        sW2t[k * DIM + d] = W2[e];
    }
    if (tid < DIM) {
        sb[tid]       = b1[tid];
        sb[DIM + tid] = b2[tid];
    }
    {
        int i = tid / DIM, k = tid % DIM;
        int gi = row0 + i;
        if (gi < N_NODES) {
            int s = idx[gi];
            se1[i][k] = emb1[(size_t)s * DIM + k];
            se2[i][k] = emb2[(size_t)s * DIM + k];
        }
    }
    __syncthreads();

    const int i = tid / DIM, d = tid % DIM;
    const int gi = row0 + i;
    if (gi >= N_NODES) return;

    float z1 = 0.f, z2 = 0.f;
#pragma unroll
    for (int k = 0; k < DIM; k++) {
        z1 = fmaf(se1[i][k], sW1t[k * DIM + d], z1);
        z2 = fmaf(se2[i][k], sW2t[k * DIM + d], z2);
    }
    z1 += sb[d];
    z2 += sb[DIM + d];
    g_P[gi * DIM + d] = xla_tanh(ALPHA * z1);
    g_Q[gi * DIM + d] = xla_tanh(ALPHA * z2);
}

// ---------------- kernel 2: fused zero-fill + scan (block-specialized) ----------------
__global__ void __launch_bounds__(RPB * 32) fused_kernel(float4* __restrict__ out4) {
    __shared__ float sP[RPB][DIM];
    __shared__ float sQ[RPB][DIM];
    __shared__ float tP[DIM][JTILE];
    __shared__ float tQ[DIM][JTILE];
    __shared__ int s_done;

    const int bid = blockIdx.x;
    const int tid = threadIdx.x;

    if (bid % 3 != 0) {
        // -------- zero block --------
        const int zid = bid - bid / 3 - 1;            // 0..NZERO-1
        const int n4 = (N_NODES * N_NODES) / 4;
        const float4 z = make_float4(0.f, 0.f, 0.f, 0.f);
        int i = zid * (RPB * 32) + tid;
        const int stride = NZERO * (RPB * 32);
        for (; i < n4; i += stride) __stcs(&out4[i], z);
        return;
    }

    // -------- scan block --------
    const int sb_id = bid / 3;                        // 0..NSCAN-1
    const int lane = tid & 31;
    const int w    = tid >> 5;
    const int row0 = sb_id * RPB;
    const int row  = row0 + w;

    for (int e = tid; e < RPB * DIM; e += RPB * 32) {
        int r = e / DIM, k = e % DIM;
        sP[r][k] = g_P[(row0 + r) * DIM + k];
        sQ[r][k] = g_Q[(row0 + r) * DIM + k];
    }
    if (tid == 0) s_done = 0;
    __syncthreads();

    float rP[DIM], rQ[DIM];
#pragma unroll
    for (int k = 0; k < DIM; k++) { rP[k] = sP[w][k]; rQ[k] = sQ[w][k]; }

    const float C = xla_tanh(8.0f);
    int  hits = 0;
    bool done = false;
    const int ntiles = (N_NODES + JTILE - 1) / JTILE;

    for (int t = 0; t < ntiles; t++) {
        const int j0 = t * JTILE;
        for (int e = tid; e < DIM * JTILE; e += RPB * 32) {
            int k = e / JTILE, j = e % JTILE;
            int gj = j0 + j;
            float vp = 0.f, vq = 0.f;
            if (gj < N_NODES) {
                vp = g_P[gj * DIM + k];
                vq = g_Q[gj * DIM + k];
            }
            tP[k][j] = vp;
            tQ[k][j] = vq;
        }
        __syncthreads();

        if (!done) {
#pragma unroll
            for (int q = 0; q < JTILE / 32; q++) {
                const int jt = q * 32 + lane;
                const int j  = j0 + jt;
                float d1 = 0.f, d2 = 0.f;
#pragma unroll
                for (int k = 0; k < DIM; k++) {
                    d1 = fmaf(rP[k], tQ[k][jt], d1);
                    d2 = fmaf(rQ[k], tP[k][jt], d2);
                }
                float a   = d1 - d2;
                float val = xla_tanh(ALPHA * a);
                bool pred = (j < N_NODES) && (val >= C);
                unsigned m = __ballot_sync(0xffffffffu, pred);
                int rank = __popc(m & ((1u << lane) - 1u));
                int slot = hits + rank;
                if (pred && slot < KSEL) {
                    g_hval[row * KSEL + slot] = val;
                    g_hidx[row * KSEL + slot] = j;
                }
                hits += __popc(m);
                if (hits >= KSEL) break;
            }
            if (hits >= KSEL) {
                done = true;
                if (lane == 0) atomicAdd(&s_done, 1);
            }
        }
        __syncthreads();
        if (s_done == RPB) break;
    }

    if (lane == 0) {
        g_hcnt[row] = hits < KSEL ? hits : KSEL;
        if (hits < KSEL) {
            int slot = atomicAdd(&g_nfail, 1);
            g_fail[slot] = row;
        }
    }
}

// ---------------- kernel 3: scatter hits + exact fallback ----------------
__global__ void __launch_bounds__(256) finish_kernel(float* __restrict__ out) {
    const int tid = threadIdx.x, lane = tid & 31, w = tid >> 5;

    // phase 1: scatter compact hits
    int row = blockIdx.x * 256 + tid;
    if (row < N_NODES) {
        int cnt = g_hcnt[row];
        float* orow = out + (size_t)row * N_NODES;
#pragma unroll 4
        for (int r = 0; r < cnt; r++)
            orow[g_hidx[row * KSEL + r]] = g_hval[row * KSEL + r];
    }

    // phase 2: exact stable top-32 for fail rows (expected: none)
    const int nfail = g_nfail;
    if (nfail == 0) return;
    __syncthreads();

    constexpr int CPT = (N_NODES + 255) / 256;
    __shared__ unsigned long long warpmax[8];
    __shared__ unsigned long long s_best;

    for (int t = blockIdx.x; t < nfail; t += gridDim.x) {
        const int frow = g_fail[t];
        float rP[DIM], rQ[DIM];
#pragma unroll
        for (int k = 0; k < DIM; k++) {
            rP[k] = g_P[frow * DIM + k];
            rQ[k] = g_Q[frow * DIM + k];
        }
        float vals[CPT];
#pragma unroll
        for (int c = 0; c < CPT; c++) {
            int j = tid + c * 256;
            float v = -1.f;
            if (j < N_NODES) {
                float d1 = 0.f, d2 = 0.f;
                for (int k = 0; k < DIM; k++) {
                    d1 = fmaf(rP[k], g_Q[j * DIM + k], d1);
                    d2 = fmaf(rQ[k], g_P[j * DIM + k], d2);
                }
                v = fmaxf(0.f, xla_tanh(ALPHA * (d1 - d2)));
            }
            vals[c] = v;
        }
        unsigned long long chosen = 0ull;
        for (int it = 0; it < KSEL; it++) {
            unsigned long long best = 0ull;
#pragma unroll
            for (int c = 0; c < CPT; c++) {
                int j = tid + c * 256;
                if (j < N_NODES && !((chosen >> c) & 1ull) && vals[c] >= 0.f) {
                    unsigned long long key =
                        ((unsigned long long)__float_as_uint(vals[c]) << 32) |
                        (unsigned long long)(0xFFFFFFFFu - (unsigned)j);
                    if (key > best) best = key;
                }
            }
#pragma unroll
            for (int off = 16; off > 0; off >>= 1) {
                unsigned long long o = __shfl_down_sync(0xffffffffu, best, off);
                if (o > best) best = o;
            }
            if (lane == 0) warpmax[w] = best;
            __syncthreads();
            if (tid == 0) {
                unsigned long long b = warpmax[0];
                for (int i = 1; i < 8; i++) if (warpmax[i] > b) b = warpmax[i];
                s_best = b;
            }
            __syncthreads();
            unsigned long long gb = s_best;
            int widx = (int)(0xFFFFFFFFu - (unsigned)(gb & 0xFFFFFFFFu));
            if ((widx & 255) == tid) {
                chosen |= 1ull << (widx >> 8);
                out[(size_t)frow * N_NODES + widx] = __uint_as_float((unsigned)(gb >> 32));
            }
            __syncthreads();
        }
        __syncthreads();
    }
}

// ---------------- launch ----------------
extern "C" void kernel_launch(void* const* d_in, const int* in_sizes, int n_in,
                              void* d_out, int out_size) {
    const int*   idx  = (const int*)  d_in[0];
    const float* emb1 = (const float*)d_in[1];
    const float* emb2 = (const float*)d_in[2];
    const float* W1   = (const float*)d_in[3];
    const float* b1   = (const float*)d_in[4];
    const float* W2   = (const float*)d_in[5];
    const float* b2   = (const float*)d_in[6];
    float* out = (float*)d_out;

    (void)in_sizes; (void)n_in; (void)out_size;

    const int prep_grid = (N_NODES + PREP_ROWS - 1) / PREP_ROWS;
    prep_kernel<<<prep_grid, PREP_ROWS * DIM>>>(idx, emb1, emb2, W1, b1, W2, b2);

    fused_kernel<<<GRIDB, RPB * 32>>>((float4*)out);

    finish_kernel<<<(N_NODES + 255) / 256, 256>>>(out);
}

// round 5
// speedup vs baseline: 1.2891x; 1.1344x over previous
#include <cuda_runtime.h>
#include <stdint.h>
#include <stddef.h>

#define N_NODES 10000
#define DIM 40
#define KSEL 32
#define ALPHA 3.0f
#define JTILE 64
#define RPB 8            // rows per mega block (one warp per row)
#define PREP_ROWS 32     // rows per prep block
#define PREP_THREADS 320 // PREP_ROWS * (DIM/4)

// ---------------- device scratch (no allocation allowed) ----------------
__device__ float g_P[N_NODES * DIM];
__device__ float g_Q[N_NODES * DIM];
__device__ int   g_fail[N_NODES];
__device__ int   g_nfail;

// ---------------- XLA EmitFastTanh replica (with-FMA variant) ----------------
__device__ __forceinline__ float xla_tanh(float x) {
    const float kClamp = 7.99881172180175781f;
    float ax = fabsf(x);
    float xc = fminf(fmaxf(x, -kClamp), kClamp);
    float x2 = xc * xc;
    float num = -2.76076847742355e-16f;
    num = fmaf(x2, num,  2.00018790482477e-13f);
    num = fmaf(x2, num, -8.60467152213735e-11f);
    num = fmaf(x2, num,  5.12229709037114e-08f);
    num = fmaf(x2, num,  1.48572235717979e-05f);
    num = fmaf(x2, num,  6.37261928875436e-04f);
    num = fmaf(x2, num,  4.89352455891786e-03f);
    num = xc * num;
    float den = 1.19825839466702e-06f;
    den = fmaf(x2, den, 1.18534705686654e-04f);
    den = fmaf(x2, den, 2.26843463243900e-03f);
    den = fmaf(x2, den, 4.89352518554385e-03f);
    float r = num / den;
    return (ax < 0.0004f) ? x : r;
}

// ---------------- kernel 1: nv prep, 4-wide vectorized ----------------
// thread = (row i, d-group of 4). Per k: 2 scalar LDS (e) + 2 LDS.128 (W rows)
// feed 8 FMAs.
__global__ void __launch_bounds__(PREP_THREADS) prep_kernel(
        const int* __restrict__ idx,
        const float* __restrict__ emb1,
        const float* __restrict__ emb2,
        const float* __restrict__ W1,
        const float* __restrict__ b1,
        const float* __restrict__ W2,
        const float* __restrict__ b2) {
    __shared__ __align__(16) float sW1t[DIM * DIM];   // [k][d]
    __shared__ __align__(16) float sW2t[DIM * DIM];
    __shared__ float sb[2 * DIM];
    __shared__ __align__(16) float se1[PREP_ROWS * DIM];
    __shared__ __align__(16) float se2[PREP_ROWS * DIM];
    __shared__ int sidx[PREP_ROWS];

    const int tid  = threadIdx.x;
    const int row0 = blockIdx.x * PREP_ROWS;

    if (blockIdx.x == 0 && tid == 0) g_nfail = 0;

    for (int e = tid; e < DIM * DIM; e += PREP_THREADS) {
        int d = e / DIM, k = e % DIM;
        sW1t[k * DIM + d] = W1[e];
        sW2t[k * DIM + d] = W2[e];
    }
    if (tid < 2 * DIM)
        sb[tid] = (tid < DIM) ? b1[tid] : b2[tid - DIM];
    if (tid < PREP_ROWS) {
        int gi = row0 + tid;
        sidx[tid] = (gi < N_NODES) ? idx[gi] : 0;
    }
    __syncthreads();

    for (int e = tid; e < PREP_ROWS * DIM; e += PREP_THREADS) {
        int i = e / DIM, k = e % DIM;
        int s = sidx[i];
        se1[e] = emb1[(size_t)s * DIM + k];
        se2[e] = emb2[(size_t)s * DIM + k];
    }
    __syncthreads();

    const int i  = tid / (DIM / 4);
    const int dg = (tid % (DIM / 4)) * 4;
    const int gi = row0 + i;
    if (gi >= N_NODES) return;

    float z1a = 0.f, z1b = 0.f, z1c = 0.f, z1d = 0.f;
    float z2a = 0.f, z2b = 0.f, z2c = 0.f, z2d = 0.f;
#pragma unroll
    for (int k = 0; k < DIM; k++) {
        float e1v = se1[i * DIM + k];
        float e2v = se2[i * DIM + k];
        float4 w1 = *reinterpret_cast<const float4*>(&sW1t[k * DIM + dg]);
        float4 w2 = *reinterpret_cast<const float4*>(&sW2t[k * DIM + dg]);
        z1a = fmaf(e1v, w1.x, z1a); z1b = fmaf(e1v, w1.y, z1b);
        z1c = fmaf(e1v, w1.z, z1c); z1d = fmaf(e1v, w1.w, z1d);
        z2a = fmaf(e2v, w2.x, z2a); z2b = fmaf(e2v, w2.y, z2b);
        z2c = fmaf(e2v, w2.z, z2c); z2d = fmaf(e2v, w2.w, z2d);
    }
    float4 p, q;
    p.x = xla_tanh(ALPHA * (z1a + sb[dg + 0]));
    p.y = xla_tanh(ALPHA * (z1b + sb[dg + 1]));
    p.z = xla_tanh(ALPHA * (z1c + sb[dg + 2]));
    p.w = xla_tanh(ALPHA * (z1d + sb[dg + 3]));
    q.x = xla_tanh(ALPHA * (z2a + sb[DIM + dg + 0]));
    q.y = xla_tanh(ALPHA * (z2b + sb[DIM + dg + 1]));
    q.z = xla_tanh(ALPHA * (z2c + sb[DIM + dg + 2]));
    q.w = xla_tanh(ALPHA * (z2d + sb[DIM + dg + 3]));
    *reinterpret_cast<float4*>(&g_P[gi * DIM + dg]) = p;
    *reinterpret_cast<float4*>(&g_Q[gi * DIM + dg]) = q;
}

// ---------------- kernel 2: mega — zero own rows + scan + direct scatter ----------------
__global__ void __launch_bounds__(RPB * 32) mega_kernel(float* __restrict__ out) {
    __shared__ float sP[RPB][DIM];
    __shared__ float sQ[RPB][DIM];
    __shared__ float tP[DIM][JTILE];
    __shared__ float tQ[DIM][JTILE];
    __shared__ int s_done;

    const int tid  = threadIdx.x;
    const int lane = tid & 31;
    const int w    = tid >> 5;
    const int row0 = blockIdx.x * RPB;
    const int row  = row0 + w;

    // zero this block's 8 output rows (contiguous 80000 floats = 20000 float4)
    {
        float4* o4 = reinterpret_cast<float4*>(out + (size_t)row0 * N_NODES);
        const float4 z = make_float4(0.f, 0.f, 0.f, 0.f);
        for (int i = tid; i < RPB * N_NODES / 4; i += RPB * 32)
            __stcs(&o4[i], z);
    }

    // stage own-row vectors
    for (int e = tid; e < RPB * DIM; e += RPB * 32) {
        int r = e / DIM, k = e % DIM;
        sP[r][k] = g_P[(row0 + r) * DIM + k];
        sQ[r][k] = g_Q[(row0 + r) * DIM + k];
    }
    if (tid == 0) s_done = 0;
    __syncthreads();   // zeros done + staging done before any scan write

    float rP[DIM], rQ[DIM];
#pragma unroll
    for (int k = 0; k < DIM; k++) { rP[k] = sP[w][k]; rQ[k] = sQ[w][k]; }

    const float C = xla_tanh(8.0f);
    int  hits = 0;
    bool done = false;
    const int ntiles = (N_NODES + JTILE - 1) / JTILE;

    for (int t = 0; t < ntiles; t++) {
        const int j0 = t * JTILE;
        for (int e = tid; e < DIM * JTILE; e += RPB * 32) {
            int k = e / JTILE, j = e % JTILE;
            int gj = j0 + j;
            float vp = 0.f, vq = 0.f;
            if (gj < N_NODES) {
                vp = g_P[gj * DIM + k];
                vq = g_Q[gj * DIM + k];
            }
            tP[k][j] = vp;
            tQ[k][j] = vq;
        }
        __syncthreads();

        if (!done) {
#pragma unroll
            for (int q = 0; q < JTILE / 32; q++) {
                const int jt = q * 32 + lane;
                const int j  = j0 + jt;
                float d1 = 0.f, d2 = 0.f;
#pragma unroll
                for (int k = 0; k < DIM; k++) {
                    d1 = fmaf(rP[k], tQ[k][jt], d1);
                    d2 = fmaf(rQ[k], tP[k][jt], d2);
                }
                float a   = d1 - d2;
                float val = xla_tanh(ALPHA * a);
                bool pred = (j < N_NODES) && (val >= C);
                unsigned m = __ballot_sync(0xffffffffu, pred);
                int rank = __popc(m & ((1u << lane) - 1u));
                if (pred && (hits + rank) < KSEL)
                    out[(size_t)row * N_NODES + j] = val;   // own row, already zeroed
                hits += __popc(m);
                if (hits >= KSEL) break;
            }
            if (hits >= KSEL) {
                done = true;
                if (lane == 0) atomicAdd(&s_done, 1);
            }
        }
        __syncthreads();
        if (s_done == RPB) break;
    }

    if (hits < KSEL && lane == 0) {
        int slot = atomicAdd(&g_nfail, 1);
        g_fail[slot] = row;
    }
}

// ---------------- kernel 3: exact stable top-32 fallback (single block, expected no-op) ----------------
__global__ void __launch_bounds__(256) fallback_kernel(float* __restrict__ out) {
    const int tid = threadIdx.x, lane = tid & 31, w = tid >> 5;
    constexpr int CPT = (N_NODES + 255) / 256;

    __shared__ unsigned long long warpmax[8];
    __shared__ unsigned long long s_best;

    const int nfail = g_nfail;
    for (int t = 0; t < nfail; t++) {
        const int frow = g_fail[t];
        float rP[DIM], rQ[DIM];
#pragma unroll
        for (int k = 0; k < DIM; k++) {
            rP[k] = g_P[frow * DIM + k];
            rQ[k] = g_Q[frow * DIM + k];
        }
        float vals[CPT];
#pragma unroll
        for (int c = 0; c < CPT; c++) {
            int j = tid + c * 256;
            float v = -1.f;
            if (j < N_NODES) {
                float d1 = 0.f, d2 = 0.f;
                for (int k = 0; k < DIM; k++) {
                    d1 = fmaf(rP[k], g_Q[j * DIM + k], d1);
                    d2 = fmaf(rQ[k], g_P[j * DIM + k], d2);
                }
                v = fmaxf(0.f, xla_tanh(ALPHA * (d1 - d2)));
            }
            vals[c] = v;
        }
        unsigned long long chosen = 0ull;
        for (int it = 0; it < KSEL; it++) {
            unsigned long long best = 0ull;
#pragma unroll
            for (int c = 0; c < CPT; c++) {
                int j = tid + c * 256;
                if (j < N_NODES && !((chosen >> c) & 1ull) && vals[c] >= 0.f) {
                    unsigned long long key =
                        ((unsigned long long)__float_as_uint(vals[c]) << 32) |
                        (unsigned long long)(0xFFFFFFFFu - (unsigned)j);
                    if (key > best) best = key;
                }
            }
#pragma unroll
            for (int off = 16; off > 0; off >>= 1) {
                unsigned long long o = __shfl_down_sync(0xffffffffu, best, off);
                if (o > best) best = o;
            }
            if (lane == 0) warpmax[w] = best;
            __syncthreads();
            if (tid == 0) {
                unsigned long long b = warpmax[0];
                for (int i = 1; i < 8; i++) if (warpmax[i] > b) b = warpmax[i];
                s_best = b;
            }
            __syncthreads();
            unsigned long long gb = s_best;
            int widx = (int)(0xFFFFFFFFu - (unsigned)(gb & 0xFFFFFFFFu));
            if ((widx & 255) == tid) {
                chosen |= 1ull << (widx >> 8);
                out[(size_t)frow * N_NODES + widx] = __uint_as_float((unsigned)(gb >> 32));
            }
            __syncthreads();
        }
        __syncthreads();
    }
}

// ---------------- launch ----------------
extern "C" void kernel_launch(void* const* d_in, const int* in_sizes, int n_in,
                              void* d_out, int out_size) {
    const int*   idx  = (const int*)  d_in[0];
    const float* emb1 = (const float*)d_in[1];
    const float* emb2 = (const float*)d_in[2];
    const float* W1   = (const float*)d_in[3];
    const float* b1   = (const float*)d_in[4];
    const float* W2   = (const float*)d_in[5];
    const float* b2   = (const float*)d_in[6];
    float* out = (float*)d_out;

    (void)in_sizes; (void)n_in; (void)out_size;

    const int prep_grid = (N_NODES + PREP_ROWS - 1) / PREP_ROWS;   // 313
    prep_kernel<<<prep_grid, PREP_THREADS>>>(idx, emb1, emb2, W1, b1, W2, b2);

    mega_kernel<<<N_NODES / RPB, RPB * 32>>>(out);

    fallback_kernel<<<1, 256>>>(out);
}

// round 6
// speedup vs baseline: 1.2979x; 1.0068x over previous
#include <cuda_runtime.h>
#include <stdint.h>
#include <stddef.h>

#define N_NODES 10000
#define DIM 40
#define KSEL 32
#define ALPHA 3.0f
#define JTILE 64
#define RPB 8                      // rows per group (one warp per row)
#define NGROUPS (N_NODES / RPB)    // 1250
#define GRIDP 296                  // 2 blocks * 148 SMs (GB300 has 152 -> always resident)
#define PCH ((N_NODES + GRIDP - 1) / GRIDP)   // 34 prep rows per block

// ---------------- device scratch (no allocation allowed) ----------------
__device__ float g_P[N_NODES * DIM];
__device__ float g_Q[N_NODES * DIM];
__device__ int   g_fail[N_NODES];
__device__ int   g_nfail;
__device__ int   g_c1 = 0;     // prep-done counter
__device__ int   g_c2 = 0;     // scan-done counter

// ---------------- XLA EmitFastTanh replica (with-FMA variant) ----------------
__device__ __forceinline__ float xla_tanh(float x) {
    const float kClamp = 7.99881172180175781f;
    float ax = fabsf(x);
    float xc = fminf(fmaxf(x, -kClamp), kClamp);
    float x2 = xc * xc;
    float num = -2.76076847742355e-16f;
    num = fmaf(x2, num,  2.00018790482477e-13f);
    num = fmaf(x2, num, -8.60467152213735e-11f);
    num = fmaf(x2, num,  5.12229709037114e-08f);
    num = fmaf(x2, num,  1.48572235717979e-05f);
    num = fmaf(x2, num,  6.37261928875436e-04f);
    num = fmaf(x2, num,  4.89352455891786e-03f);
    num = xc * num;
    float den = 1.19825839466702e-06f;
    den = fmaf(x2, den, 1.18534705686654e-04f);
    den = fmaf(x2, den, 2.26843463243900e-03f);
    den = fmaf(x2, den, 4.89352518554385e-03f);
    float r = num / den;
    return (ax < 0.0004f) ? x : r;
}

// ---------------- the one persistent kernel ----------------
__global__ void __launch_bounds__(256, 2) mono_kernel(
        const int* __restrict__ idx,
        const float* __restrict__ emb1,
        const float* __restrict__ emb2,
        const float* __restrict__ W1,
        const float* __restrict__ b1,
        const float* __restrict__ W2,
        const float* __restrict__ b2,
        float* __restrict__ out) {
    __shared__ float sW1t[DIM * DIM];           // [k][d]
    __shared__ float sW2t[DIM * DIM];
    __shared__ float sb2[2 * DIM];
    __shared__ float tP[DIM][JTILE];            // scan tiles; reused as prep e-staging
    __shared__ float tQ[DIM][JTILE];
    __shared__ float sP[RPB][DIM];
    __shared__ float sQ[RPB][DIM];
    __shared__ int s_done, s_last;
    __shared__ unsigned long long warpmax[8];
    __shared__ unsigned long long s_best;

    const int tid  = threadIdx.x;
    const int lane = tid & 31;
    const int w    = tid >> 5;
    const int bid  = blockIdx.x;

    // ======== phase 1: prep this block's chunk of P/Q ========
    if (bid == 0 && tid == 0) g_nfail = 0;

    for (int e = tid; e < DIM * DIM; e += 256) {
        int d = e / DIM, k = e % DIM;
        sW1t[k * DIM + d] = W1[e];
        sW2t[k * DIM + d] = W2[e];
    }
    if (tid < 2 * DIM)
        sb2[tid] = (tid < DIM) ? b1[tid] : b2[tid - DIM];

    const int prow0 = bid * PCH;
    int nrows = N_NODES - prow0;
    if (nrows > PCH) nrows = PCH;
    if (nrows < 0) nrows = 0;

    float* pe1 = &tP[0][0];    // 1360 <= 2560 floats
    float* pe2 = &tQ[0][0];
    for (int e = tid; e < nrows * DIM; e += 256) {
        int i = e / DIM, k = e % DIM;
        int s = idx[prow0 + i];
        pe1[e] = emb1[(size_t)s * DIM + k];
        pe2[e] = emb2[(size_t)s * DIM + k];
    }
    __syncthreads();

    for (int e = tid; e < nrows * DIM; e += 256) {
        int i = e / DIM, d = e % DIM;
        float z1 = 0.f, z2 = 0.f;
#pragma unroll
        for (int k = 0; k < DIM; k++) {
            z1 = fmaf(pe1[i * DIM + k], sW1t[k * DIM + d], z1);
            z2 = fmaf(pe2[i * DIM + k], sW2t[k * DIM + d], z2);
        }
        g_P[(prow0 + i) * DIM + d] = xla_tanh(ALPHA * (z1 + sb2[d]));
        g_Q[(prow0 + i) * DIM + d] = xla_tanh(ALPHA * (z2 + sb2[DIM + d]));
    }
    __threadfence();
    __syncthreads();
    if (tid == 0) atomicAdd(&g_c1, 1);

    // ======== phase 2: persistent loop over row-groups: zero + scan ========
    const float C = xla_tanh(8.0f);
    bool gated = false;

    for (int g = bid; g < NGROUPS; g += GRIDP) {
        const int row0 = g * RPB;
        const int row  = row0 + w;

        // zero this group's 8 rows (contiguous 20000 float4)
        {
            float4* o4 = reinterpret_cast<float4*>(out + (size_t)row0 * N_NODES);
            const float4 z = make_float4(0.f, 0.f, 0.f, 0.f);
            for (int i = tid; i < RPB * N_NODES / 4; i += 256)
                __stcs(&o4[i], z);
        }

        if (!gated) {       // wait for global prep completion (expected instant)
            if (tid == 0) {
                volatile int* c = &g_c1;
                while (*c < GRIDP) __nanosleep(100);
            }
            __threadfence();
            gated = true;
        }
        __syncthreads();    // zeros + gate before staging/scan

        for (int e = tid; e < RPB * DIM; e += 256) {
            int r = e / DIM, k = e % DIM;
            sP[r][k] = g_P[(row0 + r) * DIM + k];
            sQ[r][k] = g_Q[(row0 + r) * DIM + k];
        }
        if (tid == 0) s_done = 0;
        __syncthreads();

        float rP[DIM], rQ[DIM];
#pragma unroll
        for (int k = 0; k < DIM; k++) { rP[k] = sP[w][k]; rQ[k] = sQ[w][k]; }

        int  hits = 0;
        bool done = false;
        const int ntiles = (N_NODES + JTILE - 1) / JTILE;

        for (int t = 0; t < ntiles; t++) {
            const int j0 = t * JTILE;
            for (int e = tid; e < DIM * JTILE; e += 256) {
                int k = e / JTILE, j = e % JTILE;
                int gj = j0 + j;
                float vp = 0.f, vq = 0.f;
                if (gj < N_NODES) {
                    vp = g_P[gj * DIM + k];
                    vq = g_Q[gj * DIM + k];
                }
                tP[k][j] = vp;
                tQ[k][j] = vq;
            }
            __syncthreads();

            if (!done) {
#pragma unroll
                for (int q = 0; q < JTILE / 32; q++) {
                    const int jt = q * 32 + lane;
                    const int j  = j0 + jt;
                    float d1 = 0.f, d2 = 0.f;
#pragma unroll
                    for (int k = 0; k < DIM; k++) {
                        d1 = fmaf(rP[k], tQ[k][jt], d1);
                        d2 = fmaf(rQ[k], tP[k][jt], d2);
                    }
                    float a   = d1 - d2;
                    float val = xla_tanh(ALPHA * a);
                    bool pred = (j < N_NODES) && (val >= C);
                    unsigned m = __ballot_sync(0xffffffffu, pred);
                    int rank = __popc(m & ((1u << lane) - 1u));
                    if (pred && (hits + rank) < KSEL)
                        out[(size_t)row * N_NODES + j] = val;   // own row, already zeroed
                    hits += __popc(m);
                    if (hits >= KSEL) break;
                }
                if (hits >= KSEL) {
                    done = true;
                    if (lane == 0) atomicAdd(&s_done, 1);
                }
            }
            __syncthreads();
            if (s_done == RPB) break;
        }

        if (hits < KSEL && lane == 0) {
            int slot = atomicAdd(&g_nfail, 1);
            g_fail[slot] = row;
        }
        __syncthreads();
    }

    // ======== phase 3: last block runs exact fallback + resets counters ========
    __threadfence();
    __syncthreads();
    if (tid == 0) {
        int t = atomicAdd(&g_c2, 1);
        s_last = (t == GRIDP - 1) ? 1 : 0;
    }
    __syncthreads();
    if (!s_last) return;

    __threadfence();
    const int nfail = g_nfail;
    constexpr int CPT = (N_NODES + 255) / 256;
    for (int t = 0; t < nfail; t++) {
        const int frow = g_fail[t];
        float rP[DIM], rQ[DIM];
#pragma unroll
        for (int k = 0; k < DIM; k++) {
            rP[k] = g_P[frow * DIM + k];
            rQ[k] = g_Q[frow * DIM + k];
        }
        float vals[CPT];
#pragma unroll
        for (int c = 0; c < CPT; c++) {
            int j = tid + c * 256;
            float v = -1.f;
            if (j < N_NODES) {
                float d1 = 0.f, d2 = 0.f;
                for (int k = 0; k < DIM; k++) {
                    d1 = fmaf(rP[k], g_Q[j * DIM + k], d1);
                    d2 = fmaf(rQ[k], g_P[j * DIM + k], d2);
                }
                v = fmaxf(0.f, xla_tanh(ALPHA * (d1 - d2)));
            }
            vals[c] = v;
        }
        unsigned long long chosen = 0ull;
        for (int it = 0; it < KSEL; it++) {
            unsigned long long best = 0ull;
#pragma unroll
            for (int c = 0; c < CPT; c++) {
                int j = tid + c * 256;
                if (j < N_NODES && !((chosen >> c) & 1ull) && vals[c] >= 0.f) {
                    unsigned long long key =
                        ((unsigned long long)__float_as_uint(vals[c]) << 32) |
                        (unsigned long long)(0xFFFFFFFFu - (unsigned)j);
                    if (key > best) best = key;
                }
            }
#pragma unroll
            for (int off = 16; off > 0; off >>= 1) {
                unsigned long long o = __shfl_down_sync(0xffffffffu, best, off);
                if (o > best) best = o;
            }
            if (lane == 0) warpmax[w] = best;
            __syncthreads();
            if (tid == 0) {
                unsigned long long b = warpmax[0];
                for (int i = 1; i < 8; i++) if (warpmax[i] > b) b = warpmax[i];
                s_best = b;
            }
            __syncthreads();
            unsigned long long gb = s_best;
            int widx = (int)(0xFFFFFFFFu - (unsigned)(gb & 0xFFFFFFFFu));
            if ((widx & 255) == tid) {
                chosen |= 1ull << (widx >> 8);
                out[(size_t)frow * N_NODES + widx] = __uint_as_float((unsigned)(gb >> 32));
            }
            __syncthreads();
        }
        __syncthreads();
    }

    // reset counters for the next graph replay (deterministic)
    __syncthreads();
    if (tid == 0) { g_c1 = 0; g_c2 = 0; }
}

// ---------------- launch ----------------
extern "C" void kernel_launch(void* const* d_in, const int* in_sizes, int n_in,
                              void* d_out, int out_size) {
    const int*   idx  = (const int*)  d_in[0];
    const float* emb1 = (const float*)d_in[1];
    const float* emb2 = (const float*)d_in[2];
    const float* W1   = (const float*)d_in[3];
    const float* b1   = (const float*)d_in[4];
    const float* W2   = (const float*)d_in[5];
    const float* b2   = (const float*)d_in[6];
    float* out = (float*)d_out;

    (void)in_sizes; (void)n_in; (void)out_size;

    mono_kernel<<<GRIDP, 256>>>(idx, emb1, emb2, W1, b1, W2, b2, out);
}